// round 2
// baseline (speedup 1.0000x reference)
#include <cuda_runtime.h>
#include <cuda_bf16.h>
#include <stdint.h>

// ---------------- problem constants ----------------
#define M_DIM 32768
#define N_DIM 1024
#define K_DIM 1024

#define BM 128
#define BN 128
#define BK 32
#define STAGES 3
#define LDS_STRIDE 40                 // bf16 elements per smem row (32 + 8 pad)
#define ARR (BM * LDS_STRIDE)         // 5120 bf16 per tile array
#define STG (4 * ARR)                 // Ah, Al, Bh, Bl per stage

// ---------------- scratch (static device allocations) ----------------
__device__ __nv_bfloat16 g_xh[(size_t)M_DIM * K_DIM];
__device__ __nv_bfloat16 g_xl[(size_t)M_DIM * K_DIM];
__device__ __nv_bfloat16 g_wh[(size_t)N_DIM * K_DIM];
__device__ __nv_bfloat16 g_wl[(size_t)N_DIM * K_DIM];
__device__ float g_bnd[32];   // 31 boundaries + +inf guard
__device__ float g_lh[32];    // bf16(level) as float
__device__ float g_ll[32];    // bf16(level - bf16(level)) as float

// ---------------- NF5 table setup ----------------
__global__ void nf5_setup_kernel() {
    if (threadIdx.x != 0 || blockIdx.x != 0) return;
    float tab[32];
    // neg: ndtri(linspace(1-0.9677083, 0.5, 17))[:-1], normalized by -neg[0]
    {
        double a = 1.0 - 0.9677083;
        double step = (0.5 - a) / 16.0;
        float n0 = (float)normcdfinv(a);
        for (int i = 0; i < 16; i++) {
            float ni = (float)normcdfinv(a + step * (double)i);
            tab[i] = ni / (-n0);
        }
    }
    tab[16] = 0.0f;
    // pos: ndtri(linspace(0.5, 0.9677083, 16))[1:], normalized by pos[-1]
    {
        double b = 0.9677083;
        double step = (b - 0.5) / 15.0;
        float plast = (float)normcdfinv(b);
        for (int i = 1; i <= 15; i++) {
            float pi = (float)normcdfinv(0.5 + step * (double)i);
            tab[16 + i] = pi / plast;
        }
    }
    for (int i = 0; i < 31; i++) g_bnd[i] = (tab[i] + tab[i + 1]) * 0.5f;
    g_bnd[31] = __int_as_float(0x7f800000);  // +inf
    for (int i = 0; i < 32; i++) {
        float h = __bfloat162float(__float2bfloat16(tab[i]));
        g_lh[i] = h;
        g_ll[i] = __bfloat162float(__float2bfloat16(tab[i] - h));
    }
}

// ---------------- quantize (blockwise NF5, hi/lo bf16 split) ----------------
// Each thread handles 4 consecutive elements; 8-lane subgroup = one 32-block.
__device__ __forceinline__ void quant_body(const float4* __restrict__ in,
                                           __nv_bfloat16* __restrict__ hi,
                                           __nv_bfloat16* __restrict__ lo,
                                           int n4) {
    __shared__ float4 lut[1024];
    for (int j = threadIdx.x; j < 1024; j += blockDim.x) {
        float left = (float)j * (1.0f / 512.0f) - 1.0f;
        int idx0 = 0;
#pragma unroll
        for (int i = 0; i < 31; i++) idx0 += (g_bnd[i] < left) ? 1 : 0;
        float thr = g_bnd[idx0];
        int idx1 = (idx0 < 31) ? idx0 + 1 : 31;
        unsigned p0 = (unsigned)__bfloat16_as_ushort(__float2bfloat16(g_lh[idx0]))
                    | ((unsigned)__bfloat16_as_ushort(__float2bfloat16(g_ll[idx0])) << 16);
        unsigned p1 = (unsigned)__bfloat16_as_ushort(__float2bfloat16(g_lh[idx1]))
                    | ((unsigned)__bfloat16_as_ushort(__float2bfloat16(g_ll[idx1])) << 16);
        lut[j] = make_float4(thr, __uint_as_float(p0), __uint_as_float(p1), 0.0f);
    }
    __syncthreads();

    int gid = blockIdx.x * blockDim.x + threadIdx.x;
    if (gid >= n4) return;
    float4 v = in[gid];
    float am = fmaxf(fmaxf(fabsf(v.x), fabsf(v.y)), fmaxf(fabsf(v.z), fabsf(v.w)));
    am = fmaxf(am, __shfl_xor_sync(0xffffffffu, am, 1));
    am = fmaxf(am, __shfl_xor_sync(0xffffffffu, am, 2));
    am = fmaxf(am, __shfl_xor_sync(0xffffffffu, am, 4));
    am = fmaxf(am, 1e-12f);
    int e;
    float mts = frexpf(am, &e);
    int ce = (mts == 0.5f) ? (e - 1) : e;     // exact ceil(log2(am))
    float sc  = ldexpf(1.0f, ce);
    float inv = ldexpf(1.0f, -ce);

    float vv[4] = {v.x, v.y, v.z, v.w};
    unsigned short hs[4], ls[4];
#pragma unroll
    for (int t = 0; t < 4; t++) {
        float nrm = vv[t] * inv;                       // exact (pow2)
        int key = (int)((nrm + 1.0f) * 512.0f);
        key = min(max(key, 0), 1023);
        float4 cl = lut[key];
        unsigned pr = (cl.x < nrm) ? __float_as_uint(cl.z) : __float_as_uint(cl.y);
        float lhf = __bfloat162float(__ushort_as_bfloat16((unsigned short)(pr & 0xffffu)));
        float llf = __bfloat162float(__ushort_as_bfloat16((unsigned short)(pr >> 16)));
        hs[t] = __bfloat16_as_ushort(__float2bfloat16(lhf * sc));  // exact scaling
        ls[t] = __bfloat16_as_ushort(__float2bfloat16(llf * sc));
    }
    uint2 ph = make_uint2((unsigned)hs[0] | ((unsigned)hs[1] << 16),
                          (unsigned)hs[2] | ((unsigned)hs[3] << 16));
    uint2 pl = make_uint2((unsigned)ls[0] | ((unsigned)ls[1] << 16),
                          (unsigned)ls[2] | ((unsigned)ls[3] << 16));
    *(uint2*)((char*)hi + (size_t)gid * 8) = ph;
    *(uint2*)((char*)lo + (size_t)gid * 8) = pl;
}

__global__ void quantize_x_kernel(const float4* __restrict__ in, int n4) {
    quant_body(in, g_xh, g_xl, n4);
}
__global__ void quantize_w_kernel(const float4* __restrict__ in, int n4) {
    quant_body(in, g_wh, g_wl, n4);
}

// ---------------- GEMM ----------------
__device__ __forceinline__ void cpa8(__nv_bfloat16* dst, const __nv_bfloat16* src) {
    unsigned saddr = (unsigned)__cvta_generic_to_shared(dst);
    asm volatile("cp.async.ca.shared.global [%0], [%1], 8;\n" :: "r"(saddr), "l"(src));
}
__device__ __forceinline__ uint32_t ld32(const __nv_bfloat16* p) {
    return *(const uint32_t*)p;
}

#define MMA_BF16(d, a0, a1, a2, a3, b0, b1)                                      \
    asm volatile(                                                                \
        "mma.sync.aligned.m16n8k16.row.col.f32.bf16.bf16.f32 "                   \
        "{%0,%1,%2,%3}, {%4,%5,%6,%7}, {%8,%9}, {%0,%1,%2,%3};\n"                \
        : "+f"(d[0]), "+f"(d[1]), "+f"(d[2]), "+f"(d[3])                         \
        : "r"(a0), "r"(a1), "r"(a2), "r"(a3), "r"(b0), "r"(b1))

__global__ void __launch_bounds__(256, 1)
gemm_kernel(const float* __restrict__ bias, float* __restrict__ out) {
    extern __shared__ __nv_bfloat16 smem[];
    const int tid = threadIdx.x;
    const int lane = tid & 31, wid = tid >> 5;
    const int m0 = blockIdx.y * BM;
    const int n0 = blockIdx.x * BN;
    const int wm = (wid >> 2) * 64;   // warp m offset (2 warps in m)
    const int wn = (wid & 3) * 32;    // warp n offset (4 warps in n)
    const int r  = lane >> 2;
    const int c2 = (lane & 3) * 2;

    float acc[4][4][4];
#pragma unroll
    for (int i = 0; i < 4; i++)
#pragma unroll
        for (int j = 0; j < 4; j++)
#pragma unroll
            for (int k = 0; k < 4; k++) acc[i][j][k] = 0.0f;

    const int NK = K_DIM / BK;  // 32

    // stage loader
    auto load_stage = [&](int kt, int s) {
        int k0 = kt * BK;
        __nv_bfloat16* base = smem + s * STG;
#pragma unroll
        for (int rr = 0; rr < 4; rr++) {
            int chunk = tid + rr * 256;        // 0..1023
            int row = chunk >> 3, cc = chunk & 7;
            size_t goffA = (size_t)(m0 + row) * K_DIM + k0 + cc * 4;
            size_t goffB = (size_t)(n0 + row) * K_DIM + k0 + cc * 4;
            int soff = row * LDS_STRIDE + cc * 4;
            cpa8(base + soff,           g_xh + goffA);
            cpa8(base + ARR + soff,     g_xl + goffA);
            cpa8(base + 2 * ARR + soff, g_wh + goffB);
            cpa8(base + 3 * ARR + soff, g_wl + goffB);
        }
        asm volatile("cp.async.commit_group;\n" ::);
    };

    for (int s = 0; s < STAGES - 1; s++) load_stage(s, s);

    for (int kt = 0; kt < NK; kt++) {
        asm volatile("cp.async.wait_group %0;\n" :: "n"(STAGES - 2));
        __syncthreads();
        int nkt = kt + STAGES - 1;
        if (nkt < NK) load_stage(nkt, nkt % STAGES);
        else asm volatile("cp.async.commit_group;\n" ::);

        const __nv_bfloat16* base = smem + (kt % STAGES) * STG;
        const __nv_bfloat16* sAh = base;
        const __nv_bfloat16* sAl = base + ARR;
        const __nv_bfloat16* sBh = base + 2 * ARR;
        const __nv_bfloat16* sBl = base + 3 * ARR;

#pragma unroll
        for (int kk = 0; kk < BK; kk += 16) {
            uint32_t bh[4][2], bl[4][2];
#pragma unroll
            for (int ni = 0; ni < 4; ni++) {
                int col = wn + ni * 8 + r;
                const __nv_bfloat16* pbh = sBh + col * LDS_STRIDE + kk + c2;
                const __nv_bfloat16* pbl = sBl + col * LDS_STRIDE + kk + c2;
                bh[ni][0] = ld32(pbh);
                bh[ni][1] = ld32(pbh + 8);
                bl[ni][0] = ld32(pbl);
                bl[ni][1] = ld32(pbl + 8);
            }
#pragma unroll
            for (int mi = 0; mi < 4; mi++) {
                int row0 = wm + mi * 16 + r;
                const __nv_bfloat16* pah = sAh + row0 * LDS_STRIDE + kk + c2;
                const __nv_bfloat16* pal = sAl + row0 * LDS_STRIDE + kk + c2;
                uint32_t ah0 = ld32(pah);
                uint32_t ah1 = ld32(pah + 8 * LDS_STRIDE);
                uint32_t ah2 = ld32(pah + 8);
                uint32_t ah3 = ld32(pah + 8 * LDS_STRIDE + 8);
                uint32_t al0 = ld32(pal);
                uint32_t al1 = ld32(pal + 8 * LDS_STRIDE);
                uint32_t al2 = ld32(pal + 8);
                uint32_t al3 = ld32(pal + 8 * LDS_STRIDE + 8);
#pragma unroll
                for (int ni = 0; ni < 4; ni++) {
                    MMA_BF16(acc[mi][ni], ah0, ah1, ah2, ah3, bh[ni][0], bh[ni][1]);
                    MMA_BF16(acc[mi][ni], ah0, ah1, ah2, ah3, bl[ni][0], bl[ni][1]);
                    MMA_BF16(acc[mi][ni], al0, al1, al2, al3, bh[ni][0], bh[ni][1]);
                }
            }
        }
        __syncthreads();
    }

    // epilogue: + bias, f32 out
#pragma unroll
    for (int ni = 0; ni < 4; ni++) {
        int col = n0 + wn + ni * 8 + c2;
        float b0 = __ldg(bias + col);
        float b1 = __ldg(bias + col + 1);
#pragma unroll
        for (int mi = 0; mi < 4; mi++) {
            int row0 = m0 + wm + mi * 16 + r;
            float2 v0 = make_float2(acc[mi][ni][0] + b0, acc[mi][ni][1] + b1);
            float2 v1 = make_float2(acc[mi][ni][2] + b0, acc[mi][ni][3] + b1);
            *(float2*)(out + (size_t)row0 * N_DIM + col) = v0;
            *(float2*)(out + (size_t)(row0 + 8) * N_DIM + col) = v1;
        }
    }
}

// ---------------- launch ----------------
extern "C" void kernel_launch(void* const* d_in, const int* in_sizes, int n_in,
                              void* d_out, int out_size) {
    const float* x    = (const float*)d_in[0];
    const float* w    = (const float*)d_in[1];
    const float* bias = (const float*)d_in[2];
    float* out        = (float*)d_out;

    nf5_setup_kernel<<<1, 32>>>();

    int n4x = (M_DIM * K_DIM) / 4;     // 8388608
    int n4w = (N_DIM * K_DIM) / 4;     // 262144
    quantize_x_kernel<<<n4x / 256, 256>>>((const float4*)x, n4x);
    quantize_w_kernel<<<n4w / 256, 256>>>((const float4*)w, n4w);

    int smem_bytes = STAGES * STG * (int)sizeof(__nv_bfloat16);  // 122880
    cudaFuncSetAttribute(gemm_kernel, cudaFuncAttributeMaxDynamicSharedMemorySize, smem_bytes);
    dim3 grid(N_DIM / BN, M_DIM / BM);  // (8, 256)
    gemm_kernel<<<grid, 256, smem_bytes>>>(bias, out);
}

// round 4
// speedup vs baseline: 1.2968x; 1.2968x over previous
#include <cuda_runtime.h>
#include <cuda_bf16.h>
#include <stdint.h>

// ---------------- problem constants ----------------
#define M_DIM 32768
#define N_DIM 1024
#define K_DIM 1024

#define BM 128
#define BN 128
#define BK 64
#define STAGES 3
#define KT_TOTAL 48                       // 3 segments * (1024/64)
#define STAGE_BYTES (BM * 128 + BN * 128) // 32 KB: A tile then B tile
#define SMEM_BYTES (STAGES * STAGE_BYTES) // 96 KB

// ---------------- scratch (static device allocations) ----------------
__device__ __nv_bfloat16 g_xh[(size_t)M_DIM * K_DIM];
__device__ __nv_bfloat16 g_xl[(size_t)M_DIM * K_DIM];
__device__ __nv_bfloat16 g_wh[(size_t)N_DIM * K_DIM];
__device__ __nv_bfloat16 g_wl[(size_t)N_DIM * K_DIM];
__device__ float g_bnd[32];   // 31 boundaries + +inf guard
__device__ float g_lh[32];    // bf16(level) as float
__device__ float g_ll[32];    // bf16(level - bf16(level)) as float

// ---------------- NF5 table setup ----------------
__global__ void nf5_setup_kernel() {
    if (threadIdx.x != 0 || blockIdx.x != 0) return;
    float tab[32];
    {
        double a = 1.0 - 0.9677083;
        double step = (0.5 - a) / 16.0;
        float n0 = (float)normcdfinv(a);
        for (int i = 0; i < 16; i++) {
            float ni = (float)normcdfinv(a + step * (double)i);
            tab[i] = ni / (-n0);
        }
    }
    tab[16] = 0.0f;
    {
        double b = 0.9677083;
        double step = (b - 0.5) / 15.0;
        float plast = (float)normcdfinv(b);
        for (int i = 1; i <= 15; i++) {
            float pi = (float)normcdfinv(0.5 + step * (double)i);
            tab[16 + i] = pi / plast;
        }
    }
    for (int i = 0; i < 31; i++) g_bnd[i] = (tab[i] + tab[i + 1]) * 0.5f;
    g_bnd[31] = __int_as_float(0x7f800000);  // +inf guard
    for (int i = 0; i < 32; i++) {
        float h = __bfloat162float(__float2bfloat16(tab[i]));
        g_lh[i] = h;
        g_ll[i] = __bfloat162float(__float2bfloat16(tab[i] - h));
    }
}

// ---------------- quantize (blockwise NF5, hi/lo bf16 split) ----------------
// thread = 4 consecutive elems; 8-lane subgroup = one 32-elem block.
__global__ void __launch_bounds__(256)
quant_kernel(const float4* __restrict__ in, __nv_bfloat16* __restrict__ hi,
             __nv_bfloat16* __restrict__ lo, int n4) {
    __shared__ float4 lut[1024];
    __shared__ float sbnd[32], slh[32], sll[32];
    if (threadIdx.x < 32) {
        sbnd[threadIdx.x] = g_bnd[threadIdx.x];
        slh[threadIdx.x]  = g_lh[threadIdx.x];
        sll[threadIdx.x]  = g_ll[threadIdx.x];
    }
    __syncthreads();
    for (int j = threadIdx.x; j < 1024; j += blockDim.x) {
        float left = (float)j * (1.0f / 512.0f) - 1.0f;
        int idx0 = 0;
#pragma unroll
        for (int i = 0; i < 31; i++) idx0 += (sbnd[i] < left) ? 1 : 0;
        float thr = sbnd[idx0];
        int idx1 = (idx0 < 31) ? idx0 + 1 : 31;
        unsigned p0 = (unsigned)__bfloat16_as_ushort(__float2bfloat16(slh[idx0]))
                    | ((unsigned)__bfloat16_as_ushort(__float2bfloat16(sll[idx0])) << 16);
        unsigned p1 = (unsigned)__bfloat16_as_ushort(__float2bfloat16(slh[idx1]))
                    | ((unsigned)__bfloat16_as_ushort(__float2bfloat16(sll[idx1])) << 16);
        lut[j] = make_float4(thr, __uint_as_float(p0), __uint_as_float(p1), 0.0f);
    }
    __syncthreads();

    const int stride = gridDim.x * blockDim.x;
    for (int gid = blockIdx.x * blockDim.x + threadIdx.x; gid < n4; gid += stride) {
        float4 v = in[gid];
        float am = fmaxf(fmaxf(fabsf(v.x), fabsf(v.y)), fmaxf(fabsf(v.z), fabsf(v.w)));
        am = fmaxf(am, __shfl_xor_sync(0xffffffffu, am, 1));
        am = fmaxf(am, __shfl_xor_sync(0xffffffffu, am, 2));
        am = fmaxf(am, __shfl_xor_sync(0xffffffffu, am, 4));
        am = fmaxf(am, 1e-12f);
        // exact ceil(log2(am)) via exponent bits (am normal, positive)
        uint32_t ab = __float_as_uint(am);
        int E = (int)(ab >> 23) - 127;
        int ce = ((ab & 0x7fffffu) != 0u) ? E + 1 : E;
        float sc  = __uint_as_float((uint32_t)(ce + 127) << 23);
        float inv = __uint_as_float((uint32_t)(127 - ce) << 23);

        float vv[4] = {v.x, v.y, v.z, v.w};
        unsigned short hs[4], ls[4];
#pragma unroll
        for (int t = 0; t < 4; t++) {
            float nrm = vv[t] * inv;                     // exact (pow2)
            int key = (int)((nrm + 1.0f) * 512.0f);
            key = min(max(key, 0), 1023);
            float4 cl = lut[key];
            unsigned pr = (cl.x < nrm) ? __float_as_uint(cl.z) : __float_as_uint(cl.y);
            float lhf = __bfloat162float(__ushort_as_bfloat16((unsigned short)(pr & 0xffffu)));
            float llf = __bfloat162float(__ushort_as_bfloat16((unsigned short)(pr >> 16)));
            hs[t] = __bfloat16_as_ushort(__float2bfloat16(lhf * sc));   // exact scaling
            ls[t] = __bfloat16_as_ushort(__float2bfloat16(llf * sc));
        }
        uint2 ph = make_uint2((unsigned)hs[0] | ((unsigned)hs[1] << 16),
                              (unsigned)hs[2] | ((unsigned)hs[3] << 16));
        uint2 pl = make_uint2((unsigned)ls[0] | ((unsigned)ls[1] << 16),
                              (unsigned)ls[2] | ((unsigned)ls[3] << 16));
        *(uint2*)((char*)hi + (size_t)gid * 8) = ph;
        *(uint2*)((char*)lo + (size_t)gid * 8) = pl;
    }
}

// ---------------- GEMM (HMMA + ldmatrix + cp.async, K' = 3072 concat) ----------------
__device__ __forceinline__ uint32_t smem_u32(const void* p) {
    uint32_t a;
    asm("{ .reg .u64 t; cvta.to.shared.u64 t, %1; cvt.u32.u64 %0, t; }" : "=r"(a) : "l"(p));
    return a;
}
__device__ __forceinline__ void cpa16(uint32_t dst, const void* src) {
    asm volatile("cp.async.cg.shared.global [%0], [%1], 16;\n" :: "r"(dst), "l"(src));
}
__device__ __forceinline__ void ldsm4(uint32_t* r, uint32_t addr) {
    asm volatile("ldmatrix.sync.aligned.m8n8.x4.shared.b16 {%0,%1,%2,%3}, [%4];\n"
                 : "=r"(r[0]), "=r"(r[1]), "=r"(r[2]), "=r"(r[3]) : "r"(addr));
}

#define MMA_BF16(d, a0, a1, a2, a3, b0, b1)                                      \
    asm volatile(                                                                \
        "mma.sync.aligned.m16n8k16.row.col.f32.bf16.bf16.f32 "                   \
        "{%0,%1,%2,%3}, {%4,%5,%6,%7}, {%8,%9}, {%0,%1,%2,%3};\n"                \
        : "+f"(d[0]), "+f"(d[1]), "+f"(d[2]), "+f"(d[3])                         \
        : "r"(a0), "r"(a1), "r"(a2), "r"(a3), "r"(b0), "r"(b1))

__global__ void __launch_bounds__(256, 2)
gemm_kernel(const float* __restrict__ bias, float* __restrict__ out) {
    extern __shared__ __align__(1024) char smem[];
    const uint32_t sb = smem_u32(smem);
    const int tid  = threadIdx.x;
    const int lane = tid & 31, wid = tid >> 5;
    const int m0 = blockIdx.y * BM;
    const int n0 = blockIdx.x * BN;
    const int wm = (wid >> 2) * 64;     // warp m offset (2 warps in m)
    const int wn = (wid & 3) * 32;      // warp n offset (4 warps in n)
    const int l15 = lane & 15, lh4 = lane >> 4;

    float acc[4][4][4];
#pragma unroll
    for (int i = 0; i < 4; i++)
#pragma unroll
        for (int j = 0; j < 4; j++)
#pragma unroll
            for (int k = 0; k < 4; k++) acc[i][j][k] = 0.0f;

    // stage loader: 16B cp.async, XOR-swizzled 128B rows
    auto load_stage = [&](int tile, int s) {
        const int seg = tile >> 4;
        const int k0  = (tile & 15) * 64;
        const __nv_bfloat16* Ab = (seg == 1) ? g_xl : g_xh;
        const __nv_bfloat16* Bb = (seg == 2) ? g_wl : g_wh;
        const uint32_t stA = sb + s * STAGE_BYTES;
        const uint32_t stB = stA + BM * 128;
#pragma unroll
        for (int q = 0; q < 4; q++) {
            int idx = tid + q * 256;              // 0..1023
            int row = idx >> 3, ch = idx & 7;
            int sw = ch ^ (row & 7);
            cpa16(stA + row * 128 + sw * 16,
                  Ab + (size_t)(m0 + row) * K_DIM + k0 + ch * 8);
            cpa16(stB + row * 128 + sw * 16,
                  Bb + (size_t)(n0 + row) * K_DIM + k0 + ch * 8);
        }
        asm volatile("cp.async.commit_group;\n" ::);
    };

#pragma unroll
    for (int s = 0; s < STAGES - 1; s++) load_stage(s, s);

#pragma unroll 1
    for (int t = 0; t < KT_TOTAL; t++) {
        asm volatile("cp.async.wait_group %0;\n" :: "n"(STAGES - 2));
        __syncthreads();
        int nt = t + STAGES - 1;
        if (nt < KT_TOTAL) load_stage(nt, nt % STAGES);
        else asm volatile("cp.async.commit_group;\n" ::);

        const uint32_t stA = sb + (t % STAGES) * STAGE_BYTES;
        const uint32_t stB = stA + BM * 128;

#pragma unroll
        for (int kf = 0; kf < 4; kf++) {
            const int ch = kf * 2 + lh4;
            uint32_t a[4][4];
#pragma unroll
            for (int mf = 0; mf < 4; mf++) {
                int row = wm + mf * 16 + l15;
                ldsm4(a[mf], stA + row * 128 + ((ch ^ (row & 7)) * 16));
            }
            uint32_t b[2][4];
#pragma unroll
            for (int p = 0; p < 2; p++) {
                int row = wn + p * 16 + l15;
                ldsm4(b[p], stB + row * 128 + ((ch ^ (row & 7)) * 16));
            }
#pragma unroll
            for (int mf = 0; mf < 4; mf++) {
#pragma unroll
                for (int nf = 0; nf < 4; nf++) {
                    uint32_t b0 = b[nf >> 1][nf & 1];
                    uint32_t b1 = b[nf >> 1][(nf & 1) + 2];
                    MMA_BF16(acc[mf][nf], a[mf][0], a[mf][1], a[mf][2], a[mf][3], b0, b1);
                }
            }
        }
        __syncthreads();
    }

    // epilogue: + bias, f32 out
    const int r  = lane >> 2;
    const int c2 = (lane & 3) * 2;
#pragma unroll
    for (int nf = 0; nf < 4; nf++) {
        int col = n0 + wn + nf * 8 + c2;
        float b0 = __ldg(bias + col);
        float b1 = __ldg(bias + col + 1);
#pragma unroll
        for (int mf = 0; mf < 4; mf++) {
            int row0 = m0 + wm + mf * 16 + r;
            float2 v0 = make_float2(acc[mf][nf][0] + b0, acc[mf][nf][1] + b1);
            float2 v1 = make_float2(acc[mf][nf][2] + b0, acc[mf][nf][3] + b1);
            *(float2*)(out + (size_t)row0 * N_DIM + col) = v0;
            *(float2*)(out + (size_t)(row0 + 8) * N_DIM + col) = v1;
        }
    }
}

// ---------------- launch ----------------
extern "C" void kernel_launch(void* const* d_in, const int* in_sizes, int n_in,
                              void* d_out, int out_size) {
    const float* x    = (const float*)d_in[0];
    const float* w    = (const float*)d_in[1];
    const float* bias = (const float*)d_in[2];
    float* out        = (float*)d_out;

    nf5_setup_kernel<<<1, 32>>>();

    void *pxh, *pxl, *pwh, *pwl;
    cudaGetSymbolAddress(&pxh, g_xh);
    cudaGetSymbolAddress(&pxl, g_xl);
    cudaGetSymbolAddress(&pwh, g_wh);
    cudaGetSymbolAddress(&pwl, g_wl);

    const int n4x = (M_DIM * K_DIM) / 4;     // 8388608
    const int n4w = (N_DIM * K_DIM) / 4;     // 262144
    quant_kernel<<<2048, 256>>>((const float4*)x, (__nv_bfloat16*)pxh,
                                (__nv_bfloat16*)pxl, n4x);
    quant_kernel<<<256, 256>>>((const float4*)w, (__nv_bfloat16*)pwh,
                               (__nv_bfloat16*)pwl, n4w);

    cudaFuncSetAttribute(gemm_kernel,
                         cudaFuncAttributeMaxDynamicSharedMemorySize, SMEM_BYTES);
    dim3 grid(N_DIM / BN, M_DIM / BM);   // (8, 256)
    gemm_kernel<<<grid, 256, SMEM_BYTES>>>(bias, out);
}